// round 12
// baseline (speedup 1.0000x reference)
#include <cuda_runtime.h>
#include <cuda_bf16.h>
#include <cstdint>

// Problem shape (fixed for this problem id)
#define BB   16
#define SS   768
#define DE   16
#define HID  128
#define BSN  (BB*SS)          // 12288 rows
#define ROWF (SS*DE)          // 12288 floats per (b,i) row
#define ROWF4 (ROWF/4)        // 3072 float4 per row

// ---- scratch (no allocations allowed) ----
__device__ float g_dist[BSN];
__device__ float g_imp[BSN];
__device__ float g_wnc[HID];
__device__ float g_v[64];
__device__ float g_C[1];
__device__ unsigned char g_mask[BSN];

// ============================================================================
// Kernel 1: prep — 26 independent blocks (proven). Triggers PDL completion
// IMMEDIATELY so edge's CTAs launch and stream concurrently with prep.
// ============================================================================
__global__ void __launch_bounds__(128) prep_kernel(
                            const void* __restrict__ pocket_raw,
                            const float* __restrict__ W_node,
                            const float* __restrict__ b_node,
                            const float* __restrict__ W_e2,
                            const float* __restrict__ b_e2,
                            const float* __restrict__ W_imp,
                            const float* __restrict__ b_imp)
{
    // Let the dependent edge_kernel start right away — it defers its
    // grid-dependency sync until after its streaming loop.
    cudaTriggerProgrammaticLaunchCompletion();

    const int blk = blockIdx.x;
    const int t = threadIdx.x;

    if (blk < 24) {
        __shared__ int s_fone, s_other;
        if (t == 0) { s_fone = 0; s_other = 0; }
        __syncthreads();
        {
            const unsigned int* w = (const unsigned int*)pocket_raw;
            unsigned int x[24];
            #pragma unroll
            for (int u = 0; u < 24; u++) x[u] = w[t + u * 128];
            int lf = 0, lo = 0;
            #pragma unroll
            for (int u = 0; u < 24; u++) {
                if (x[u] == 0x3F800000u) lf++;
                else if (x[u] != 0u && x[u] != 1u) lo++;
            }
            if (lf) atomicAdd(&s_fone, lf);
            if (lo) atomicAdd(&s_other, lo);
        }
        __syncthreads();
        // mode: 0=float32 (saw 1.0f words), 2=bool/u8 (packed bytes), 1=int32
        const int mode = (s_fone > 0) ? 0 : ((s_other > 0) ? 2 : 1);

        const int base = blk * 512;
        if (mode == 0) {
            const float* p = (const float*)pocket_raw;
            #pragma unroll
            for (int u = 0; u < 4; u++) {
                const int idx = base + t + u * 128;
                g_mask[idx] = (p[idx] != 0.0f) ? 1 : 0;
            }
        } else if (mode == 1) {
            const int* p = (const int*)pocket_raw;
            #pragma unroll
            for (int u = 0; u < 4; u++) {
                const int idx = base + t + u * 128;
                g_mask[idx] = (p[idx] != 0) ? 1 : 0;
            }
        } else {
            const unsigned char* p = (const unsigned char*)pocket_raw;
            #pragma unroll
            for (int u = 0; u < 4; u++) {
                const int idx = base + t + u * 128;
                g_mask[idx] = (p[idx] != 0) ? 1 : 0;
            }
        }
    } else if (blk == 24) {
        float s = 0.0f;
        #pragma unroll
        for (int k = 0; k < 32; k++) s += W_node[t * 32 + k] * W_imp[k];
        g_wnc[t] = s;
    } else {
        if (t < 64) {
            float s = 0.0f;
            #pragma unroll
            for (int k = 0; k < 32; k++) s += W_e2[t * 32 + k] * W_imp[32 + k];
            g_v[t] = s;
        }
        if (t == 0) {
            float c = b_imp[0];
            #pragma unroll
            for (int k = 0; k < 32; k++) c += b_node[k] * W_imp[k];
            #pragma unroll
            for (int k = 0; k < 32; k++) c += b_e2[k] * W_imp[32 + k];
            g_C[0] = c;
        }
    }
}

// ============================================================================
// Kernel 2: edge pass + importance. Main loop has NO prep dependency:
// channel-0 values are stashed to smem (predicated STS), and the masked min
// + epilogue run AFTER cudaGridDependencySynchronize(). The 604 MB stream
// starts immediately and fully overlaps prep.
// ============================================================================
__global__ void __launch_bounds__(256) edge_kernel(const float* __restrict__ edge,
                                                   const float* __restrict__ node,
                                                   const float* __restrict__ seqmask,
                                                   const float* __restrict__ We1,
                                                   const float* __restrict__ be1)
{
    const int i = blockIdx.x;
    const int b = blockIdx.y;
    const int t = threadIdx.x;
    const int row_id = b * SS + i;

    __shared__ float schan0[SS];               // channel-0 values, all j
    __shared__ unsigned char sm[SS];
    __shared__ float swnc[HID], sw1[64], sb1[64], sv[64];
    __shared__ float ssum[8], smn[8];

    const float4* __restrict__ row =
        (const float4*)(edge + (size_t)row_id * (size_t)ROWF);

    const float INF = __int_as_float(0x7f800000);
    float sum0 = 0.0f, sum1 = 0.0f;
    #pragma unroll
    for (int it = 0; it < ROWF4 / 256; it++) {
        const int k = t + it * 256;
        float4 v = __ldcs(row + k);
        if (it & 1) sum1 += (v.x + v.y) + (v.z + v.w);
        else        sum0 += (v.x + v.y) + (v.z + v.w);
        if ((t & 3) == 0) {                    // this lane owns channel 0 here
            schan0[(t >> 2) + it * 64] = v.x;  // j = k>>2
        }
    }
    float sum = sum0 + sum1;

    // warp reduce the sum (order identical to prior rounds)
    #pragma unroll
    for (int o = 16; o; o >>= 1) sum += __shfl_xor_sync(0xFFFFFFFFu, sum, o);
    const int wid = t >> 5, lid = t & 31;
    if (lid == 0) ssum[wid] = sum;

    // ---- NOW wait for prep (g_mask/g_wnc/g_v/g_C) ----
    cudaGridDependencySynchronize();

    for (int k = t; k < SS; k += 256) sm[k] = g_mask[b * SS + k];
    if (t < HID) swnc[t] = g_wnc[t];
    if (t >= 128 && t < 192) {
        const int j = t - 128;
        sw1[j] = We1[j]; sb1[j] = be1[j]; sv[j] = g_v[j];
    }
    __syncthreads();   // covers schan0, ssum, and the smem loads above

    // ---- masked min: 3 j's per thread, then block reduce (order-free) ----
    float mn = INF;
    #pragma unroll
    for (int u = 0; u < 3; u++) {
        const int j = t + u * 256;
        mn = fminf(mn, sm[j] ? schan0[j] : INF);
    }
    #pragma unroll
    for (int o = 16; o; o >>= 1) mn = fminf(mn, __shfl_xor_sync(0xFFFFFFFFu, mn, o));
    if (lid == 0) smn[wid] = mn;

    // ---- warp 0: node dot partial (coalesced; 1 float4 per lane) ----
    float nacc = 0.0f;
    if (t < 32) {
        const float4 nv = __ldg((const float4*)(node + (size_t)row_id * HID) + t);
        nacc = nv.x * swnc[t * 4 + 0] + nv.y * swnc[t * 4 + 1]
             + nv.z * swnc[t * 4 + 2] + nv.w * swnc[t * 4 + 3];
    }
    __syncthreads();   // covers smn

    // ---- epilogue: warp 0 computes importance + dist for this row ----
    if (t < 32) {
        float S = 0.0f, M = INF;
        #pragma unroll
        for (int k = 0; k < 8; k++) { S += ssum[k]; M = fminf(M, smn[k]); }

        const float es = S * (1.0f / (float)ROWF);
        const float h0 = fmaxf(es * sw1[t]      + sb1[t],      0.0f);
        const float h1 = fmaxf(es * sw1[t + 32] + sb1[t + 32], 0.0f);
        float acc = nacc + h0 * sv[t] + h1 * sv[t + 32];
        #pragma unroll
        for (int o = 16; o; o >>= 1) acc += __shfl_xor_sync(0xFFFFFFFFu, acc, o);

        if (t == 0) {
            const float logit = acc + g_C[0];
            const float imp = 1.0f / (1.0f + expf(-logit));   // accurate exp
            g_imp[row_id]  = imp * seqmask[row_id];
            g_dist[row_id] = M;
        }
    }
    // Let the dependent final_kernel begin its launch/setup.
    cudaTriggerProgrammaticLaunchCompletion();
}

// ============================================================================
// Kernel 3: finalize — one block per batch; shuffle reductions + PDL (R11).
// ============================================================================
__global__ void __launch_bounds__(256) final_kernel(float* __restrict__ out, int out_size)
{
    const int b = blockIdx.x, t = threadIdx.x;
    const int w = t >> 5, l = t & 31;
    __shared__ float wred[8];
    __shared__ float s_mean;
    __shared__ int   wcnt[8], wany[8];

    // Wait for edge_kernel's g_imp/g_dist writes.
    cudaGridDependencySynchronize();

    // ---- mean of imp over the batch (deterministic fixed order) ----
    float s = 0.0f;
    #pragma unroll
    for (int it = 0; it < SS / 256; it++) s += g_imp[b * SS + t + it * 256];
    #pragma unroll
    for (int o = 16; o; o >>= 1) s += __shfl_xor_sync(0xFFFFFFFFu, s, o);
    if (l == 0) wred[w] = s;
    __syncthreads();
    if (t == 0) {
        float S = 0.0f;
        #pragma unroll
        for (int k = 0; k < 8; k++) S += wred[k];
        s_mean = S * (1.0f / (float)SS);
    }
    __syncthreads();
    const float mean = s_mean;

    // ---- merged count + any(pocket) ----
    int cnt = 0, anyp = 0;
    #pragma unroll
    for (int it = 0; it < SS / 256; it++) {
        const int idx = b * SS + t + it * 256;
        const bool p = g_mask[idx] != 0;
        const float d = g_dist[idx];
        const bool core  = d < 6.0f;
        const bool shell = (d >= 6.0f) && (d < 10.0f) && (g_imp[idx] > mean);
        cnt += (p | core | shell) ? 1 : 0;
        anyp |= p ? 1 : 0;
    }
    #pragma unroll
    for (int o = 16; o; o >>= 1) {
        cnt  += __shfl_xor_sync(0xFFFFFFFFu, cnt, o);
        anyp |= __shfl_xor_sync(0xFFFFFFFFu, anyp, o);
    }
    if (l == 0) { wcnt[w] = cnt; wany[w] = anyp; }
    __syncthreads();

    if (t == 0) {
        int C = 0, A = 0;
        #pragma unroll
        for (int k = 0; k < 8; k++) { C += wcnt[k]; A |= wany[k]; }
        float chunk;
        if (A) {
            int ml = C; if (ml > 256) ml = 256;                // merged_len clamp
            chunk = fminf(fmaxf((float)ml, 64.0f), 256.0f);    // clamp(adj=64, 256)
        } else {
            chunk = fminf(fmaxf(64.0f * mean, 32.0f), 128.0f); // clip(64*imp, 32, 128)
        }
        out[b] = chunk;
    }
    // pad remaining outputs (MAX_SEQ_LEN) in parallel from block 0
    if (b == 0) {
        for (int k = BB + t; k < out_size; k += 256) out[k] = 256.0f;
    }
}

// ============================================================================
extern "C" void kernel_launch(void* const* d_in, const int* in_sizes, int n_in,
                              void* d_out, int out_size)
{
    const float* node    = (const float*)d_in[0];   // [16,768,128]
    const float* edge    = (const float*)d_in[1];   // [16,768,768,16]
    const float* seqmask = (const float*)d_in[2];   // [16,768]
    const void*  pocket  = d_in[3];                 // [16,768] dtype detected at runtime
    const float* W_node  = (const float*)d_in[4];
    const float* b_node  = (const float*)d_in[5];
    const float* W_e1    = (const float*)d_in[6];
    const float* b_e1    = (const float*)d_in[7];
    const float* W_e2    = (const float*)d_in[8];
    const float* b_e2    = (const float*)d_in[9];
    const float* W_imp   = (const float*)d_in[10];
    const float* b_imp   = (const float*)d_in[11];
    float* out = (float*)d_out;

    // prep: normal launch (triggers PDL completion at its start)
    prep_kernel<<<26, 128>>>(pocket, W_node, b_node, W_e2, b_e2, W_imp, b_imp);

    // edge: PDL — starts streaming immediately, syncs on prep only at epilogue
    {
        cudaLaunchConfig_t cfg = {};
        cfg.gridDim  = dim3(SS, BB, 1);
        cfg.blockDim = dim3(256, 1, 1);
        cfg.stream   = 0;
        cudaLaunchAttribute attr[1];
        attr[0].id = cudaLaunchAttributeProgrammaticStreamSerialization;
        attr[0].val.programmaticStreamSerializationAllowed = 1;
        cfg.attrs = attr;
        cfg.numAttrs = 1;
        cudaLaunchKernelEx(&cfg, edge_kernel, edge, node, seqmask, W_e1, b_e1);
    }

    // final: PDL — overlap launch/setup with edge's tail
    {
        cudaLaunchConfig_t cfg = {};
        cfg.gridDim  = dim3(BB, 1, 1);
        cfg.blockDim = dim3(256, 1, 1);
        cfg.stream   = 0;
        cudaLaunchAttribute attr[1];
        attr[0].id = cudaLaunchAttributeProgrammaticStreamSerialization;
        attr[0].val.programmaticStreamSerializationAllowed = 1;
        cfg.attrs = attr;
        cfg.numAttrs = 1;
        cudaLaunchKernelEx(&cfg, final_kernel, (float*)d_out, out_size);
    }
}

// round 13
// speedup vs baseline: 1.0470x; 1.0470x over previous
#include <cuda_runtime.h>
#include <cuda_bf16.h>
#include <cstdint>

// Problem shape (fixed for this problem id)
#define BB   16
#define SS   768
#define DE   16
#define HID  128
#define BSN  (BB*SS)          // 12288 rows
#define ROWF (SS*DE)          // 12288 floats per (b,i) row
#define ROWF4 (ROWF/4)        // 3072 float4 per row

// ---- scratch (no allocations allowed) ----
__device__ float g_dist[BSN];
__device__ float g_imp[BSN];
__device__ float g_wnc[HID];
__device__ float g_v[64];
__device__ float g_C[1];
__device__ unsigned char g_mask[BSN];

// ============================================================================
// Kernel 1: prep — 26 independent blocks (proven). Triggers PDL completion
// at START so edge's CTAs are rasterized/parked at their grid-sync while
// prep executes (edge still fully waits on prep's writes via the sync).
// ============================================================================
__global__ void __launch_bounds__(128) prep_kernel(
                            const void* __restrict__ pocket_raw,
                            const float* __restrict__ W_node,
                            const float* __restrict__ b_node,
                            const float* __restrict__ W_e2,
                            const float* __restrict__ b_e2,
                            const float* __restrict__ W_imp,
                            const float* __restrict__ b_imp)
{
    cudaTriggerProgrammaticLaunchCompletion();

    const int blk = blockIdx.x;
    const int t = threadIdx.x;

    if (blk < 24) {
        __shared__ int s_fone, s_other;
        if (t == 0) { s_fone = 0; s_other = 0; }
        __syncthreads();
        {
            const unsigned int* w = (const unsigned int*)pocket_raw;
            unsigned int x[24];
            #pragma unroll
            for (int u = 0; u < 24; u++) x[u] = w[t + u * 128];
            int lf = 0, lo = 0;
            #pragma unroll
            for (int u = 0; u < 24; u++) {
                if (x[u] == 0x3F800000u) lf++;
                else if (x[u] != 0u && x[u] != 1u) lo++;
            }
            if (lf) atomicAdd(&s_fone, lf);
            if (lo) atomicAdd(&s_other, lo);
        }
        __syncthreads();
        // mode: 0=float32 (saw 1.0f words), 2=bool/u8 (packed bytes), 1=int32
        const int mode = (s_fone > 0) ? 0 : ((s_other > 0) ? 2 : 1);

        const int base = blk * 512;
        if (mode == 0) {
            const float* p = (const float*)pocket_raw;
            #pragma unroll
            for (int u = 0; u < 4; u++) {
                const int idx = base + t + u * 128;
                g_mask[idx] = (p[idx] != 0.0f) ? 1 : 0;
            }
        } else if (mode == 1) {
            const int* p = (const int*)pocket_raw;
            #pragma unroll
            for (int u = 0; u < 4; u++) {
                const int idx = base + t + u * 128;
                g_mask[idx] = (p[idx] != 0) ? 1 : 0;
            }
        } else {
            const unsigned char* p = (const unsigned char*)pocket_raw;
            #pragma unroll
            for (int u = 0; u < 4; u++) {
                const int idx = base + t + u * 128;
                g_mask[idx] = (p[idx] != 0) ? 1 : 0;
            }
        }
    } else if (blk == 24) {
        float s = 0.0f;
        #pragma unroll
        for (int k = 0; k < 32; k++) s += W_node[t * 32 + k] * W_imp[k];
        g_wnc[t] = s;
    } else {
        if (t < 64) {
            float s = 0.0f;
            #pragma unroll
            for (int k = 0; k < 32; k++) s += W_e2[t * 32 + k] * W_imp[32 + k];
            g_v[t] = s;
        }
        if (t == 0) {
            float c = b_imp[0];
            #pragma unroll
            for (int k = 0; k < 32; k++) c += b_node[k] * W_imp[k];
            #pragma unroll
            for (int k = 0; k < 32; k++) c += b_e2[k] * W_imp[32 + k];
            g_C[0] = c;
        }
    }
}

// ============================================================================
// Kernel 2: edge pass + importance — 604 MB stream (R11 exact: grid sync at
// top, in-loop masked min, warp-0 node dot + epilogue).
// ============================================================================
__global__ void __launch_bounds__(256) edge_kernel(const float* __restrict__ edge,
                                                   const float* __restrict__ node,
                                                   const float* __restrict__ seqmask,
                                                   const float* __restrict__ We1,
                                                   const float* __restrict__ be1)
{
    const int i = blockIdx.x;
    const int b = blockIdx.y;
    const int t = threadIdx.x;
    const int row_id = b * SS + i;

    // Wait for prep's writes (g_mask/g_wnc/g_v/g_C) to be visible.
    cudaGridDependencySynchronize();

    __shared__ unsigned char sm[SS];
    __shared__ float swnc[HID], sw1[64], sb1[64], sv[64];
    for (int k = t; k < SS; k += 256) sm[k] = g_mask[b * SS + k];
    if (t < HID) swnc[t] = g_wnc[t];
    if (t >= 128 && t < 192) {
        const int j = t - 128;
        sw1[j] = We1[j]; sb1[j] = be1[j]; sv[j] = g_v[j];
    }
    __syncthreads();

    // ---- warp 0: node dot partial (coalesced; 1 float4 per lane) ----
    float nacc = 0.0f;
    if (t < 32) {
        const float4 nv = __ldg((const float4*)(node + (size_t)row_id * HID) + t);
        nacc = nv.x * swnc[t * 4 + 0] + nv.y * swnc[t * 4 + 1]
             + nv.z * swnc[t * 4 + 2] + nv.w * swnc[t * 4 + 3];
    }

    const float4* __restrict__ row =
        (const float4*)(edge + (size_t)row_id * (size_t)ROWF);

    const float INF = __int_as_float(0x7f800000);
    float sum0 = 0.0f, sum1 = 0.0f;
    float mn = INF;
    #pragma unroll
    for (int it = 0; it < ROWF4 / 256; it++) {
        const int k = t + it * 256;
        float4 v = __ldcs(row + k);
        if (it & 1) sum1 += (v.x + v.y) + (v.z + v.w);
        else        sum0 += (v.x + v.y) + (v.z + v.w);
        if ((k & 3) == 0) {                 // channel 0 of edge feature j
            const int j = k >> 2;
            const float cand = sm[j] ? v.x : INF;   // select, no branch
            mn = fminf(mn, cand);
        }
    }
    float sum = sum0 + sum1;

    // warp reduce
    #pragma unroll
    for (int o = 16; o; o >>= 1) {
        sum += __shfl_xor_sync(0xFFFFFFFFu, sum, o);
        mn   = fminf(mn, __shfl_xor_sync(0xFFFFFFFFu, mn, o));
    }
    __shared__ float ssum[8], smn[8];
    const int wid = t >> 5, lid = t & 31;
    if (lid == 0) { ssum[wid] = sum; smn[wid] = mn; }
    __syncthreads();

    // ---- epilogue: warp 0 computes importance for this row ----
    if (t < 32) {
        float S = 0.0f, M = INF;
        #pragma unroll
        for (int k = 0; k < 8; k++) { S += ssum[k]; M = fminf(M, smn[k]); }

        const float es = S * (1.0f / (float)ROWF);
        const float h0 = fmaxf(es * sw1[t]      + sb1[t],      0.0f);
        const float h1 = fmaxf(es * sw1[t + 32] + sb1[t + 32], 0.0f);
        float acc = nacc + h0 * sv[t] + h1 * sv[t + 32];
        #pragma unroll
        for (int o = 16; o; o >>= 1) acc += __shfl_xor_sync(0xFFFFFFFFu, acc, o);

        if (t == 0) {
            const float logit = acc + g_C[0];
            const float imp = 1.0f / (1.0f + expf(-logit));   // accurate exp
            g_imp[row_id]  = imp * seqmask[row_id];
            g_dist[row_id] = M;
        }
    }
    // Let the dependent final_kernel begin its launch/setup.
    cudaTriggerProgrammaticLaunchCompletion();
}

// ============================================================================
// Kernel 3: finalize — one block per batch; shuffle reductions + PDL.
// ============================================================================
__global__ void __launch_bounds__(256) final_kernel(float* __restrict__ out, int out_size)
{
    const int b = blockIdx.x, t = threadIdx.x;
    const int w = t >> 5, l = t & 31;
    __shared__ float wred[8];
    __shared__ float s_mean;
    __shared__ int   wcnt[8], wany[8];

    // Wait for edge_kernel's g_imp/g_dist writes.
    cudaGridDependencySynchronize();

    // ---- mean of imp over the batch (deterministic fixed order) ----
    float s = 0.0f;
    #pragma unroll
    for (int it = 0; it < SS / 256; it++) s += g_imp[b * SS + t + it * 256];
    #pragma unroll
    for (int o = 16; o; o >>= 1) s += __shfl_xor_sync(0xFFFFFFFFu, s, o);
    if (l == 0) wred[w] = s;
    __syncthreads();
    if (t == 0) {
        float S = 0.0f;
        #pragma unroll
        for (int k = 0; k < 8; k++) S += wred[k];
        s_mean = S * (1.0f / (float)SS);
    }
    __syncthreads();
    const float mean = s_mean;

    // ---- merged count + any(pocket) ----
    int cnt = 0, anyp = 0;
    #pragma unroll
    for (int it = 0; it < SS / 256; it++) {
        const int idx = b * SS + t + it * 256;
        const bool p = g_mask[idx] != 0;
        const float d = g_dist[idx];
        const bool core  = d < 6.0f;
        const bool shell = (d >= 6.0f) && (d < 10.0f) && (g_imp[idx] > mean);
        cnt += (p | core | shell) ? 1 : 0;
        anyp |= p ? 1 : 0;
    }
    #pragma unroll
    for (int o = 16; o; o >>= 1) {
        cnt  += __shfl_xor_sync(0xFFFFFFFFu, cnt, o);
        anyp |= __shfl_xor_sync(0xFFFFFFFFu, anyp, o);
    }
    if (l == 0) { wcnt[w] = cnt; wany[w] = anyp; }
    __syncthreads();

    if (t == 0) {
        int C = 0, A = 0;
        #pragma unroll
        for (int k = 0; k < 8; k++) { C += wcnt[k]; A |= wany[k]; }
        float chunk;
        if (A) {
            int ml = C; if (ml > 256) ml = 256;                // merged_len clamp
            chunk = fminf(fmaxf((float)ml, 64.0f), 256.0f);    // clamp(adj=64, 256)
        } else {
            chunk = fminf(fmaxf(64.0f * mean, 32.0f), 128.0f); // clip(64*imp, 32, 128)
        }
        out[b] = chunk;
    }
    // pad remaining outputs (MAX_SEQ_LEN) in parallel from block 0
    if (b == 0) {
        for (int k = BB + t; k < out_size; k += 256) out[k] = 256.0f;
    }
}

// ============================================================================
extern "C" void kernel_launch(void* const* d_in, const int* in_sizes, int n_in,
                              void* d_out, int out_size)
{
    const float* node    = (const float*)d_in[0];   // [16,768,128]
    const float* edge    = (const float*)d_in[1];   // [16,768,768,16]
    const float* seqmask = (const float*)d_in[2];   // [16,768]
    const void*  pocket  = d_in[3];                 // [16,768] dtype detected at runtime
    const float* W_node  = (const float*)d_in[4];
    const float* b_node  = (const float*)d_in[5];
    const float* W_e1    = (const float*)d_in[6];
    const float* b_e1    = (const float*)d_in[7];
    const float* W_e2    = (const float*)d_in[8];
    const float* b_e2    = (const float*)d_in[9];
    const float* W_imp   = (const float*)d_in[10];
    const float* b_imp   = (const float*)d_in[11];
    float* out = (float*)d_out;

    // prep: normal launch (triggers PDL completion at its start so edge's
    // CTAs rasterize early and park at their grid-sync)
    prep_kernel<<<26, 128>>>(pocket, W_node, b_node, W_e2, b_e2, W_imp, b_imp);

    // edge: PDL
    {
        cudaLaunchConfig_t cfg = {};
        cfg.gridDim  = dim3(SS, BB, 1);
        cfg.blockDim = dim3(256, 1, 1);
        cfg.stream   = 0;
        cudaLaunchAttribute attr[1];
        attr[0].id = cudaLaunchAttributeProgrammaticStreamSerialization;
        attr[0].val.programmaticStreamSerializationAllowed = 1;
        cfg.attrs = attr;
        cfg.numAttrs = 1;
        cudaLaunchKernelEx(&cfg, edge_kernel, edge, node, seqmask, W_e1, b_e1);
    }

    // final: PDL — overlap launch/setup with edge's tail
    {
        cudaLaunchConfig_t cfg = {};
        cfg.gridDim  = dim3(BB, 1, 1);
        cfg.blockDim = dim3(256, 1, 1);
        cfg.stream   = 0;
        cudaLaunchAttribute attr[1];
        attr[0].id = cudaLaunchAttributeProgrammaticStreamSerialization;
        attr[0].val.programmaticStreamSerializationAllowed = 1;
        cfg.attrs = attr;
        cfg.numAttrs = 1;
        cudaLaunchKernelEx(&cfg, final_kernel, (float*)d_out, out_size);
    }
}